// round 16
// baseline (speedup 1.0000x reference)
#include <cuda_runtime.h>
#include <cstdint>
#include <cfloat>

// VectorQuantizer on B200 — round 16: single-pass k-loop with BRANCHLESS
// best-2 group-min tracking (pass 2 deleted; predicated SELs, no branches).
// Exact-fp32 recheck of flagged groups keeps indices bit-identical.
#define KCODES    512
#define DCH       64
#define SPATIAL   32768
#define NVEC      262144
#define Q_ELEMS   16777216
#define LOSS_OFF  Q_ELEMS
#define IDX_OFF   (Q_ELEMS + 1)
#define TILE_M    128
#define NTILES    (NVEC / TILE_M)   // 2048
#define GRID_MAIN 296               // 2 CTAs per SM
#define BLOCK_MAIN 256
#define MARGIN    3e-3f

#define A_STRIDE   144
#define B_STRIDE   144
#define SM_A       0                // 128*144 = 18432
#define SM_B       18432            // 512*144 = 73728
#define SM_SSC     92160            // 2048
#define SM_BIDX    94208            // 512
#define SM_LOSS    94720            // 32
#define SM_TOTAL   94752

__device__ double g_blocksums[GRID_MAIN];

__device__ __forceinline__ uint32_t smem_u32(const void* p) {
    uint32_t a;
    asm("{ .reg .u64 t; cvta.to.shared.u64 t, %1; cvt.u32.u64 %0, t; }" : "=r"(a) : "l"(p));
    return a;
}
__device__ __forceinline__ uint32_t bf16pair(float lo, float hi) {
    uint32_t r;
    asm("cvt.rn.bf16x2.f32 %0, %1, %2;" : "=r"(r) : "f"(hi), "f"(lo));
    return r;
}
__device__ __forceinline__ void ldmx4(uint32_t* r, uint32_t a) {
    asm volatile("ldmatrix.sync.aligned.m8n8.x4.shared.b16 {%0,%1,%2,%3}, [%4];"
        : "=r"(r[0]), "=r"(r[1]), "=r"(r[2]), "=r"(r[3]) : "r"(a));
}
__device__ __forceinline__ void mma16816(float* d, const uint32_t* a, const uint32_t* b) {
    asm volatile("mma.sync.aligned.m16n8k16.row.col.f32.bf16.bf16.f32 "
        "{%0,%1,%2,%3}, {%4,%5,%6,%7}, {%8,%9}, {%0,%1,%2,%3};"
        : "+f"(d[0]), "+f"(d[1]), "+f"(d[2]), "+f"(d[3])
        : "r"(a[0]), "r"(a[1]), "r"(a[2]), "r"(a[3]), "r"(b[0]), "r"(b[1]));
}
__inline__ __device__ float warpReduceSum(float v) {
    #pragma unroll
    for (int o = 16; o > 0; o >>= 1) v += __shfl_down_sync(0xffffffffu, v, o);
    return v;
}
// EXACT frozen distance: a0..a3 over j%4, (a0+a1)+(a2+a3), (sx+sc)-2dot
__device__ __forceinline__ float exact_d(const float* __restrict__ crow,
                                         const float (&x)[DCH], float sx, float sck) {
    float a0 = 0.f, a1 = 0.f, a2 = 0.f, a3 = 0.f;
    #pragma unroll
    for (int j = 0; j < DCH; j += 4) {
        float4 c = *(const float4*)(crow + j);
        a0 = fmaf(c.x, x[j + 0], a0);
        a1 = fmaf(c.y, x[j + 1], a1);
        a2 = fmaf(c.z, x[j + 2], a2);
        a3 = fmaf(c.w, x[j + 3], a3);
    }
    return (sx + sck) - 2.0f * ((a0 + a1) + (a2 + a3));
}
// branchless best-2 group-min tracker (values m1<=m2<=m3, ids for m1,m2)
__device__ __forceinline__ void trk(float g, int nt, float& m1, float& m2,
                                    float& m3, int& g1, int& g2) {
    bool lt1 = g < m1, lt2 = g < m2, lt3 = g < m3;
    m3 = lt2 ? m2 : (lt3 ? g : m3);
    m2 = lt1 ? m1 : (lt2 ? g : m2);
    g2 = lt1 ? g1 : (lt2 ? nt : g2);
    m1 = lt1 ? g  : m1;
    g1 = lt1 ? nt : g1;
}

__global__ __launch_bounds__(BLOCK_MAIN, 2)
void vq_hmma(const float* __restrict__ in, const float* __restrict__ cb,
             float* __restrict__ out) {
    extern __shared__ char smem[];
    uint32_t sbase = smem_u32(smem);
    float* ssc   = (float*)(smem + SM_SSC);
    int*   sbidx = (int*)  (smem + SM_BIDX);
    float* sloss = (float*)(smem + SM_LOSS);

    int tid = threadIdx.x, lane = tid & 31, w = tid >> 5;   // w in 0..7
    int dv = tid & 127, h = tid >> 7;
    int qr = lane >> 2, qc2 = (lane & 3) * 2;

    // ---- codebook bf16 -> SMEM B; exact fp32 norms (reference order) ----
    const float4* cb4 = (const float4*)cb;
    for (int i = tid; i < KCODES * 16; i += BLOCK_MAIN) {
        int k = i >> 4, j4 = i & 15;
        float4 v = cb4[i];
        char* dst = smem + SM_B + k * B_STRIDE + j4 * 8;
        *(uint32_t*)(dst)     = bf16pair(v.x, v.y);
        *(uint32_t*)(dst + 4) = bf16pair(v.z, v.w);
    }
    for (int k = tid; k < KCODES; k += BLOCK_MAIN) {
        const float* c = cb + (size_t)k * DCH;
        float s = 0.f;
        #pragma unroll
        for (int j = 0; j < DCH; j++) s = fmaf(c[j], c[j], s);
        ssc[k] = s;
    }
    __syncthreads();

    float threadLoss = 0.f;

    for (int tile = blockIdx.x; tile < NTILES; tile += GRID_MAIN) {
        int v0 = tile * TILE_M;
        int b  = v0 >> 15;
        int s0 = v0 & (SPATIAL - 1);

        // ---- A fill: thread -> row dv, channel half h ----
        {
            const float* xg = in + (size_t)b * DCH * SPATIAL + s0 + dv;
            #pragma unroll
            for (int jj = 0; jj < 32; jj += 2) {
                int j = h * 32 + jj;
                float x0 = xg[(size_t)j * SPATIAL];
                float x1 = xg[(size_t)(j + 1) * SPATIAL];
                *(uint32_t*)(smem + SM_A + dv * A_STRIDE + j * 2) = bf16pair(x0, x1);
            }
        }
        __syncthreads();

        // ---- A fragments: warp w -> rows 16w..16w+15 ----
        uint32_t afr[4][4];
        int g = lane >> 3, r = lane & 7;
        #pragma unroll
        for (int kc = 0; kc < 4; kc++) {
            uint32_t aaddr = sbase + SM_A
                + (uint32_t)((w * 16 + r + (g & 1) * 8) * A_STRIDE)
                + (uint32_t)((kc * 16 + (g >> 1) * 8) * 2);
            ldmx4(afr[kc], aaddr);
        }
        uint32_t bbase = sbase + SM_B
            + (uint32_t)(((g >> 1) * 8 + r) * B_STRIDE)
            + (uint32_t)((g & 1) * 16);

        // ---- single pass: scores + branchless group-min tracking ----
        float m1_0 = FLT_MAX, m2_0 = FLT_MAX, m3_0 = FLT_MAX;
        float m1_8 = FLT_MAX, m2_8 = FLT_MAX, m3_8 = FLT_MAX;
        int g1_0 = 0, g2_0 = 0, g1_8 = 0, g2_8 = 0;

        for (int nt = 0; nt < 64; nt += 2) {
            float d0[4] = {0.f, 0.f, 0.f, 0.f};
            float d1[4] = {0.f, 0.f, 0.f, 0.f};
            uint32_t brow = bbase + (uint32_t)(nt * 8 * B_STRIDE);
            #pragma unroll
            for (int kc = 0; kc < 4; kc++) {
                uint32_t bf[4];
                ldmx4(bf, brow + kc * 32);
                mma16816(d0, afr[kc], bf + 0);
                mma16816(d1, afr[kc], bf + 2);
            }
            float2 sA = *(const float2*)(ssc + nt * 8 + qc2);
            float2 sB = *(const float2*)(ssc + nt * 8 + 8 + qc2);
            // row r0
            float e00 = sA.x - 2.f * d0[0], e01 = sA.y - 2.f * d0[1];
            float e02 = sB.x - 2.f * d1[0], e03 = sB.y - 2.f * d1[1];
            float gl0 = fminf(fminf(e00, e01), fminf(e02, e03));
            trk(gl0, nt, m1_0, m2_0, m3_0, g1_0, g2_0);
            // row r8
            float e10 = sA.x - 2.f * d0[2], e11 = sA.y - 2.f * d0[3];
            float e12 = sB.x - 2.f * d1[2], e13 = sB.y - 2.f * d1[3];
            float gl1 = fminf(fminf(e10, e11), fminf(e12, e13));
            trk(gl1, nt, m1_8, m2_8, m3_8, g1_8, g2_8);
        }
        // quad-reduce approx min per row
        float gm0 = m1_0, gm8 = m1_8;
        #pragma unroll
        for (int o = 1; o < 4; o <<= 1) {
            gm0 = fminf(gm0, __shfl_xor_sync(0xffffffffu, gm0, o));
            gm8 = fminf(gm8, __shfl_xor_sync(0xffffffffu, gm8, o));
        }
        float thr0 = gm0 + MARGIN, thr8 = gm8 + MARGIN;

        // ---- exact recheck of flagged groups (outside hot loop) ----
        int r0 = w * 16 + qr, r8 = r0 + 8;
        float bd0 = FLT_MAX, bd8 = FLT_MAX;
        int   bi0 = KCODES,  bi8 = KCODES;

        if (m1_0 <= thr0) {
            const float* xg = in + (size_t)b * DCH * SPATIAL + s0 + r0;
            float x[DCH];
            #pragma unroll
            for (int j = 0; j < DCH; j++) x[j] = xg[(size_t)j * SPATIAL];
            float sx = 0.f;                        // frozen sequential order
            #pragma unroll
            for (int j = 0; j < DCH; j++) sx = fmaf(x[j], x[j], sx);
            if (m3_0 <= thr0) {   // rare: >=3 groups in margin -> scan own 128 k's
                for (int nt = 0; nt < 64; nt++) {
                    int k = nt * 8 + qc2;
                    float d = exact_d(cb + (size_t)k * DCH, x, sx, ssc[k]);
                    if (d < bd0) { bd0 = d; bi0 = k; }
                    d = exact_d(cb + (size_t)(k + 1) * DCH, x, sx, ssc[k + 1]);
                    if (d < bd0) { bd0 = d; bi0 = k + 1; }
                }
            } else {
                #pragma unroll
                for (int ci = 0; ci < 2; ci++) {
                    float mv = ci ? m2_0 : m1_0;
                    int   nt = ci ? g2_0 : g1_0;
                    if (mv <= thr0) {
                        int ks[4] = {nt * 8 + qc2, nt * 8 + qc2 + 1,
                                     nt * 8 + 8 + qc2, nt * 8 + 8 + qc2 + 1};
                        #pragma unroll
                        for (int m = 0; m < 4; m++) {
                            int k = ks[m];
                            float d = exact_d(cb + (size_t)k * DCH, x, sx, ssc[k]);
                            if (d < bd0 || (d == bd0 && k < bi0)) { bd0 = d; bi0 = k; }
                        }
                    }
                }
            }
        }
        if (m1_8 <= thr8) {
            const float* xg = in + (size_t)b * DCH * SPATIAL + s0 + r8;
            float x[DCH];
            #pragma unroll
            for (int j = 0; j < DCH; j++) x[j] = xg[(size_t)j * SPATIAL];
            float sx = 0.f;
            #pragma unroll
            for (int j = 0; j < DCH; j++) sx = fmaf(x[j], x[j], sx);
            if (m3_8 <= thr8) {
                for (int nt = 0; nt < 64; nt++) {
                    int k = nt * 8 + qc2;
                    float d = exact_d(cb + (size_t)k * DCH, x, sx, ssc[k]);
                    if (d < bd8) { bd8 = d; bi8 = k; }
                    d = exact_d(cb + (size_t)(k + 1) * DCH, x, sx, ssc[k + 1]);
                    if (d < bd8) { bd8 = d; bi8 = k + 1; }
                }
            } else {
                #pragma unroll
                for (int ci = 0; ci < 2; ci++) {
                    float mv = ci ? m2_8 : m1_8;
                    int   nt = ci ? g2_8 : g1_8;
                    if (mv <= thr8) {
                        int ks[4] = {nt * 8 + qc2, nt * 8 + qc2 + 1,
                                     nt * 8 + 8 + qc2, nt * 8 + 8 + qc2 + 1};
                        #pragma unroll
                        for (int m = 0; m < 4; m++) {
                            int k = ks[m];
                            float d = exact_d(cb + (size_t)k * DCH, x, sx, ssc[k]);
                            if (d < bd8 || (d == bd8 && k < bi8)) { bd8 = d; bi8 = k; }
                        }
                    }
                }
            }
        }
        // quad combine with first-min (smallest-k) tie-break
        #pragma unroll
        for (int o = 1; o < 4; o <<= 1) {
            float od = __shfl_xor_sync(0xffffffffu, bd0, o);
            int   oi = __shfl_xor_sync(0xffffffffu, bi0, o);
            if (od < bd0 || (od == bd0 && oi < bi0)) { bd0 = od; bi0 = oi; }
            od = __shfl_xor_sync(0xffffffffu, bd8, o);
            oi = __shfl_xor_sync(0xffffffffu, bi8, o);
            if (od < bd8 || (od == bd8 && oi < bi8)) { bd8 = od; bi8 = oi; }
        }
        if ((lane & 3) == 0) {
            sbidx[r0] = bi0;
            sbidx[r8] = bi8;
            out[IDX_OFF + v0 + r0] = (float)bi0;
            out[IDX_OFF + v0 + r8] = (float)bi8;
        }
        __syncthreads();

        // ---- epilogue: thread -> row dv, half h; STE store x + (c - x) ----
        {
            int bidx = sbidx[dv];
            const float* crow = cb + (size_t)bidx * DCH + h * 32;
            const float* xg = in + (size_t)b * DCH * SPATIAL + s0 + dv
                            + (size_t)h * 32 * SPATIAL;
            float* qout = out + (size_t)b * DCH * SPATIAL + s0 + dv
                        + (size_t)h * 32 * SPATIAL;
            #pragma unroll
            for (int q4 = 0; q4 < 8; q4++) {
                float4 c = *(const float4*)(crow + q4 * 4);
                float xv, dd;
                xv = xg[(size_t)(q4 * 4 + 0) * SPATIAL]; dd = c.x - xv;
                qout[(size_t)(q4 * 4 + 0) * SPATIAL] = xv + dd; threadLoss = fmaf(dd, dd, threadLoss);
                xv = xg[(size_t)(q4 * 4 + 1) * SPATIAL]; dd = c.y - xv;
                qout[(size_t)(q4 * 4 + 1) * SPATIAL] = xv + dd; threadLoss = fmaf(dd, dd, threadLoss);
                xv = xg[(size_t)(q4 * 4 + 2) * SPATIAL]; dd = c.z - xv;
                qout[(size_t)(q4 * 4 + 2) * SPATIAL] = xv + dd; threadLoss = fmaf(dd, dd, threadLoss);
                xv = xg[(size_t)(q4 * 4 + 3) * SPATIAL]; dd = c.w - xv;
                qout[(size_t)(q4 * 4 + 3) * SPATIAL] = xv + dd; threadLoss = fmaf(dd, dd, threadLoss);
            }
        }
        __syncthreads();   // protect A before next fill
    }

    // ---- loss reduction ----
    float ws = warpReduceSum(threadLoss);
    if (lane == 0) sloss[w] = ws;
    __syncthreads();
    if (tid == 0) {
        double t = 0.0;
        for (int i = 0; i < 8; i++) t += (double)sloss[i];
        g_blocksums[blockIdx.x] = t;
    }
}

__global__ void vq_finalize(float* __restrict__ out) {
    if (threadIdx.x == 0 && blockIdx.x == 0) {
        double t = 0.0;
        for (int i = 0; i < GRID_MAIN; i++) t += g_blocksums[i];
        out[LOSS_OFF] = (float)(1.25 * t / (double)Q_ELEMS);
    }
}

__global__ void vq_nop() {}

extern "C" void kernel_launch(void* const* d_in, const int* in_sizes, int n_in,
                              void* d_out, int out_size) {
    const float* in = (const float*)d_in[0];
    const float* cb = (const float*)d_in[1];
    float* out = (float*)d_out;

    static bool attr_set = false;
    if (!attr_set) {
        cudaFuncSetAttribute(vq_hmma, cudaFuncAttributeMaxDynamicSharedMemorySize, SM_TOTAL);
        attr_set = true;
    }

    vq_nop<<<1, 32>>>();
    vq_nop<<<1, 32>>>();
    vq_nop<<<1, 32>>>();
    vq_hmma<<<GRID_MAIN, BLOCK_MAIN, SM_TOTAL>>>(in, cb, out);
    vq_finalize<<<1, 32>>>(out);
}

// round 17
// speedup vs baseline: 2.0932x; 2.0932x over previous
#include <cuda_runtime.h>
#include <cstdint>
#include <cfloat>

// VectorQuantizer on B200 — round 17: single MMA pass + SMEM quad-min table
// (pass 2 deleted; group flags live in SMEM, not registers -> no k-loop spill).
#define KCODES    512
#define DCH       64
#define SPATIAL   32768
#define NVEC      262144
#define Q_ELEMS   16777216
#define LOSS_OFF  Q_ELEMS
#define IDX_OFF   (Q_ELEMS + 1)
#define TILE_M    128
#define NTILES    (NVEC / TILE_M)   // 2048
#define GRID_MAIN 296               // 2 CTAs per SM
#define BLOCK_MAIN 256
#define MARGIN    3e-3f

#define A_STRIDE   144
#define B_STRIDE   144
#define QT_STRIDE  33               // floats; (row*33+nt)&31 spreads banks
#define SM_A       0                // 128*144 = 18432
#define SM_B       18432            // 512*144 = 73728
#define SM_SSC     92160            // 2048
#define SM_QT      94208            // 128*33*4 = 16896
#define SM_BIDX    111104           // 512
#define SM_LOSS    111616           // 32
#define SM_TOTAL   111648

__device__ double g_blocksums[GRID_MAIN];

__device__ __forceinline__ uint32_t smem_u32(const void* p) {
    uint32_t a;
    asm("{ .reg .u64 t; cvta.to.shared.u64 t, %1; cvt.u32.u64 %0, t; }" : "=r"(a) : "l"(p));
    return a;
}
__device__ __forceinline__ uint32_t bf16pair(float lo, float hi) {
    uint32_t r;
    asm("cvt.rn.bf16x2.f32 %0, %1, %2;" : "=r"(r) : "f"(hi), "f"(lo));
    return r;
}
__device__ __forceinline__ void ldmx4(uint32_t* r, uint32_t a) {
    asm volatile("ldmatrix.sync.aligned.m8n8.x4.shared.b16 {%0,%1,%2,%3}, [%4];"
        : "=r"(r[0]), "=r"(r[1]), "=r"(r[2]), "=r"(r[3]) : "r"(a));
}
__device__ __forceinline__ void mma16816(float* d, const uint32_t* a, const uint32_t* b) {
    asm volatile("mma.sync.aligned.m16n8k16.row.col.f32.bf16.bf16.f32 "
        "{%0,%1,%2,%3}, {%4,%5,%6,%7}, {%8,%9}, {%0,%1,%2,%3};"
        : "+f"(d[0]), "+f"(d[1]), "+f"(d[2]), "+f"(d[3])
        : "r"(a[0]), "r"(a[1]), "r"(a[2]), "r"(a[3]), "r"(b[0]), "r"(b[1]));
}
__inline__ __device__ float warpReduceSum(float v) {
    #pragma unroll
    for (int o = 16; o > 0; o >>= 1) v += __shfl_down_sync(0xffffffffu, v, o);
    return v;
}
// EXACT frozen distance: a0..a3 over j%4, (a0+a1)+(a2+a3), (sx+sc)-2dot
__device__ __forceinline__ float exact_d(const float* __restrict__ crow,
                                         const float (&x)[DCH], float sx, float sck) {
    float a0 = 0.f, a1 = 0.f, a2 = 0.f, a3 = 0.f;
    #pragma unroll
    for (int j = 0; j < DCH; j += 4) {
        float4 c = *(const float4*)(crow + j);
        a0 = fmaf(c.x, x[j + 0], a0);
        a1 = fmaf(c.y, x[j + 1], a1);
        a2 = fmaf(c.z, x[j + 2], a2);
        a3 = fmaf(c.w, x[j + 3], a3);
    }
    return (sx + sck) - 2.0f * ((a0 + a1) + (a2 + a3));
}

__global__ __launch_bounds__(BLOCK_MAIN, 2)
void vq_hmma(const float* __restrict__ in, const float* __restrict__ cb,
             float* __restrict__ out) {
    extern __shared__ char smem[];
    uint32_t sbase = smem_u32(smem);
    float* ssc   = (float*)(smem + SM_SSC);
    float* qt    = (float*)(smem + SM_QT);
    int*   sbidx = (int*)  (smem + SM_BIDX);
    float* sloss = (float*)(smem + SM_LOSS);

    int tid = threadIdx.x, lane = tid & 31, w = tid >> 5;   // w in 0..7
    int dv = tid & 127, h = tid >> 7;
    int qr = lane >> 2, qc2 = (lane & 3) * 2;

    // ---- codebook bf16 -> SMEM B; exact fp32 norms (reference order) ----
    const float4* cb4 = (const float4*)cb;
    for (int i = tid; i < KCODES * 16; i += BLOCK_MAIN) {
        int k = i >> 4, j4 = i & 15;
        float4 v = cb4[i];
        char* dst = smem + SM_B + k * B_STRIDE + j4 * 8;
        *(uint32_t*)(dst)     = bf16pair(v.x, v.y);
        *(uint32_t*)(dst + 4) = bf16pair(v.z, v.w);
    }
    for (int k = tid; k < KCODES; k += BLOCK_MAIN) {
        const float* c = cb + (size_t)k * DCH;
        float s = 0.f;
        #pragma unroll
        for (int j = 0; j < DCH; j++) s = fmaf(c[j], c[j], s);
        ssc[k] = s;
    }
    __syncthreads();

    float threadLoss = 0.f;

    for (int tile = blockIdx.x; tile < NTILES; tile += GRID_MAIN) {
        int v0 = tile * TILE_M;
        int b  = v0 >> 15;
        int s0 = v0 & (SPATIAL - 1);

        // ---- A fill: thread -> row dv, channel half h ----
        {
            const float* xg = in + (size_t)b * DCH * SPATIAL + s0 + dv;
            #pragma unroll
            for (int jj = 0; jj < 32; jj += 2) {
                int j = h * 32 + jj;
                float x0 = xg[(size_t)j * SPATIAL];
                float x1 = xg[(size_t)(j + 1) * SPATIAL];
                *(uint32_t*)(smem + SM_A + dv * A_STRIDE + j * 2) = bf16pair(x0, x1);
            }
        }
        __syncthreads();

        // ---- A fragments: warp w -> rows 16w..16w+15 ----
        uint32_t afr[4][4];
        int g = lane >> 3, r = lane & 7;
        #pragma unroll
        for (int kc = 0; kc < 4; kc++) {
            uint32_t aaddr = sbase + SM_A
                + (uint32_t)((w * 16 + r + (g & 1) * 8) * A_STRIDE)
                + (uint32_t)((kc * 16 + (g >> 1) * 8) * 2);
            ldmx4(afr[kc], aaddr);
        }
        uint32_t bbase = sbase + SM_B
            + (uint32_t)(((g >> 1) * 8 + r) * B_STRIDE)
            + (uint32_t)((g & 1) * 16);

        int r0 = w * 16 + qr, r8 = r0 + 8;

        // ---- SINGLE pass: scores + row min + SMEM quad-min table ----
        float m0 = FLT_MAX, m8 = FLT_MAX;
        for (int nt = 0; nt < 64; nt += 2) {
            float d0[4] = {0.f, 0.f, 0.f, 0.f};
            float d1[4] = {0.f, 0.f, 0.f, 0.f};
            uint32_t brow = bbase + (uint32_t)(nt * 8 * B_STRIDE);
            #pragma unroll
            for (int kc = 0; kc < 4; kc++) {
                uint32_t bf[4];
                ldmx4(bf, brow + kc * 32);
                mma16816(d0, afr[kc], bf + 0);
                mma16816(d1, afr[kc], bf + 2);
            }
            float2 sA = *(const float2*)(ssc + nt * 8 + qc2);
            float2 sB = *(const float2*)(ssc + nt * 8 + 8 + qc2);
            float gl0 = fminf(fminf(sA.x - 2.f * d0[0], sA.y - 2.f * d0[1]),
                              fminf(sB.x - 2.f * d1[0], sB.y - 2.f * d1[1]));
            float gl1 = fminf(fminf(sA.x - 2.f * d0[2], sA.y - 2.f * d0[3]),
                              fminf(sB.x - 2.f * d1[2], sB.y - 2.f * d1[3]));
            m0 = fminf(m0, gl0);
            m8 = fminf(m8, gl1);
            // quad group-min -> table
            float q0 = fminf(gl0, __shfl_xor_sync(0xffffffffu, gl0, 1));
            q0 = fminf(q0, __shfl_xor_sync(0xffffffffu, q0, 2));
            float q1 = fminf(gl1, __shfl_xor_sync(0xffffffffu, gl1, 1));
            q1 = fminf(q1, __shfl_xor_sync(0xffffffffu, q1, 2));
            if ((lane & 3) == 0) {
                qt[r0 * QT_STRIDE + (nt >> 1)] = q0;
                qt[r8 * QT_STRIDE + (nt >> 1)] = q1;
            }
        }
        // quad-reduce approx min per row
        #pragma unroll
        for (int o = 1; o < 4; o <<= 1) {
            m0 = fminf(m0, __shfl_xor_sync(0xffffffffu, m0, o));
            m8 = fminf(m8, __shfl_xor_sync(0xffffffffu, m8, o));
        }
        float thr0 = m0 + MARGIN, thr8 = m8 + MARGIN;
        __syncwarp();   // table stores visible to the quad

        // ---- exact recheck: scan table, check all 4 own cols of flagged groups ----
        float bd0 = FLT_MAX, bd8 = FLT_MAX;
        int   bi0 = KCODES,  bi8 = KCODES;
        {
            const float* xg = in + (size_t)b * DCH * SPATIAL + s0 + r0;
            float x[DCH];
            #pragma unroll
            for (int j = 0; j < DCH; j++) x[j] = xg[(size_t)j * SPATIAL];
            float sx = 0.f;                        // frozen sequential order
            #pragma unroll
            for (int j = 0; j < DCH; j++) sx = fmaf(x[j], x[j], sx);
            const float* qrow = qt + r0 * QT_STRIDE;
            for (int ntp = 0; ntp < 32; ntp++) {
                if (qrow[ntp] <= thr0) {
                    int kb = ntp * 16;
                    int ks[4] = {kb + qc2, kb + qc2 + 1, kb + 8 + qc2, kb + 8 + qc2 + 1};
                    #pragma unroll
                    for (int m = 0; m < 4; m++) {
                        int k = ks[m];
                        float d = exact_d(cb + (size_t)k * DCH, x, sx, ssc[k]);
                        if (d < bd0 || (d == bd0 && k < bi0)) { bd0 = d; bi0 = k; }
                    }
                }
            }
        }
        {
            const float* xg = in + (size_t)b * DCH * SPATIAL + s0 + r8;
            float x[DCH];
            #pragma unroll
            for (int j = 0; j < DCH; j++) x[j] = xg[(size_t)j * SPATIAL];
            float sx = 0.f;
            #pragma unroll
            for (int j = 0; j < DCH; j++) sx = fmaf(x[j], x[j], sx);
            const float* qrow = qt + r8 * QT_STRIDE;
            for (int ntp = 0; ntp < 32; ntp++) {
                if (qrow[ntp] <= thr8) {
                    int kb = ntp * 16;
                    int ks[4] = {kb + qc2, kb + qc2 + 1, kb + 8 + qc2, kb + 8 + qc2 + 1};
                    #pragma unroll
                    for (int m = 0; m < 4; m++) {
                        int k = ks[m];
                        float d = exact_d(cb + (size_t)k * DCH, x, sx, ssc[k]);
                        if (d < bd8 || (d == bd8 && k < bi8)) { bd8 = d; bi8 = k; }
                    }
                }
            }
        }
        // quad combine with first-min (smallest-k) tie-break
        #pragma unroll
        for (int o = 1; o < 4; o <<= 1) {
            float od = __shfl_xor_sync(0xffffffffu, bd0, o);
            int   oi = __shfl_xor_sync(0xffffffffu, bi0, o);
            if (od < bd0 || (od == bd0 && oi < bi0)) { bd0 = od; bi0 = oi; }
            od = __shfl_xor_sync(0xffffffffu, bd8, o);
            oi = __shfl_xor_sync(0xffffffffu, bi8, o);
            if (od < bd8 || (od == bd8 && oi < bi8)) { bd8 = od; bi8 = oi; }
        }
        if ((lane & 3) == 0) {
            sbidx[r0] = bi0;
            sbidx[r8] = bi8;
            out[IDX_OFF + v0 + r0] = (float)bi0;
            out[IDX_OFF + v0 + r8] = (float)bi8;
        }
        __syncthreads();

        // ---- epilogue: thread -> row dv, half h; STE store x + (c - x) ----
        {
            int bidx = sbidx[dv];
            const float* crow = cb + (size_t)bidx * DCH + h * 32;
            const float* xg = in + (size_t)b * DCH * SPATIAL + s0 + dv
                            + (size_t)h * 32 * SPATIAL;
            float* qout = out + (size_t)b * DCH * SPATIAL + s0 + dv
                        + (size_t)h * 32 * SPATIAL;
            #pragma unroll
            for (int q4 = 0; q4 < 8; q4++) {
                float4 c = *(const float4*)(crow + q4 * 4);
                float xv, dd;
                xv = xg[(size_t)(q4 * 4 + 0) * SPATIAL]; dd = c.x - xv;
                qout[(size_t)(q4 * 4 + 0) * SPATIAL] = xv + dd; threadLoss = fmaf(dd, dd, threadLoss);
                xv = xg[(size_t)(q4 * 4 + 1) * SPATIAL]; dd = c.y - xv;
                qout[(size_t)(q4 * 4 + 1) * SPATIAL] = xv + dd; threadLoss = fmaf(dd, dd, threadLoss);
                xv = xg[(size_t)(q4 * 4 + 2) * SPATIAL]; dd = c.z - xv;
                qout[(size_t)(q4 * 4 + 2) * SPATIAL] = xv + dd; threadLoss = fmaf(dd, dd, threadLoss);
                xv = xg[(size_t)(q4 * 4 + 3) * SPATIAL]; dd = c.w - xv;
                qout[(size_t)(q4 * 4 + 3) * SPATIAL] = xv + dd; threadLoss = fmaf(dd, dd, threadLoss);
            }
        }
        __syncthreads();   // protect A/qt before next fill
    }

    // ---- loss reduction ----
    float ws = warpReduceSum(threadLoss);
    if (lane == 0) sloss[w] = ws;
    __syncthreads();
    if (tid == 0) {
        double t = 0.0;
        for (int i = 0; i < 8; i++) t += (double)sloss[i];
        g_blocksums[blockIdx.x] = t;
    }
}

__global__ void vq_finalize(float* __restrict__ out) {
    if (threadIdx.x == 0 && blockIdx.x == 0) {
        double t = 0.0;
        for (int i = 0; i < GRID_MAIN; i++) t += g_blocksums[i];
        out[LOSS_OFF] = (float)(1.25 * t / (double)Q_ELEMS);
    }
}

__global__ void vq_nop() {}

extern "C" void kernel_launch(void* const* d_in, const int* in_sizes, int n_in,
                              void* d_out, int out_size) {
    const float* in = (const float*)d_in[0];
    const float* cb = (const float*)d_in[1];
    float* out = (float*)d_out;

    static bool attr_set = false;
    if (!attr_set) {
        cudaFuncSetAttribute(vq_hmma, cudaFuncAttributeMaxDynamicSharedMemorySize, SM_TOTAL);
        attr_set = true;
    }

    vq_nop<<<1, 32>>>();
    vq_nop<<<1, 32>>>();
    vq_nop<<<1, 32>>>();
    vq_hmma<<<GRID_MAIN, BLOCK_MAIN, SM_TOTAL>>>(in, cb, out);
    vq_finalize<<<1, 32>>>(out);
}